// round 1
// baseline (speedup 1.0000x reference)
#include <cuda_runtime.h>

// Problem constants (fixed by reference_code)
#define T_GRID   8          // occupancy grid is 8x8x8
#define SUBB     7
#define CH       28
#define TILE_EL  4096       // 16*16*16
#define NT       5          // region spans tiles [0,5) per dim (slice 8..72)
#define S0       8          // slice start offset
// output: (7,1,28,64,64,64) = 51,380,224 floats = 12,845,056 float4 quads

__device__ int g_tile_map[NT * NT * NT];   // tile index or -1

// One-thread setup: detect occupancy dtype, prefix-sum, build region tile map.
// 512 iterations of scalar work — negligible next to the 268 MB stream.
__global__ void setup_kernel(const unsigned char* __restrict__ occ_bytes, int n_occ)
{
    if (threadIdx.x != 0 || blockIdx.x != 0) return;

    // Layout detection: uint8 view popcount of all 512 bytes.
    // If occupancy was widened to int32, those 512 bytes hold only the first
    // 128 flags -> count <= 128 < n_occ (154). If it is byte-sized (bool/u8/i8),
    // count == n_occ exactly.
    int cnt8 = 0;
    for (int i = 0; i < T_GRID * T_GRID * T_GRID; i++)
        cnt8 += (occ_bytes[i] != 0);
    const bool as_u8 = (cnt8 == n_occ);
    const int* occ32 = (const int*)occ_bytes;

    int prefix[T_GRID * T_GRID * T_GRID];
    int run = 0;
    for (int i = 0; i < T_GRID * T_GRID * T_GRID; i++) {
        int o = as_u8 ? (occ_bytes[i] != 0) : (occ32[i] != 0);
        run += o;
        prefix[i] = o ? (run - 1) : -1;
    }

    for (int tx = 0; tx < NT; tx++)
        for (int ty = 0; ty < NT; ty++)
            for (int tz = 0; tz < NT; tz++) {
                int lin = (tx * T_GRID + ty) * T_GRID + tz;
                g_tile_map[(tx * NT + ty) * NT + tz] = prefix[lin];
            }
}

// Flat gather: one float4 per thread.
// tid bit layout: [0:4)=z-quad, [4:10)=y, [10:16)=x, [16:..)=jc (j*28+c)
// Warp stores 512 contiguous bytes (two consecutive y rows of 256 B each).
// Loads: 4-float z chunks are 16B-aligned in the source tile (S0=8 ≡ 0 mod 4)
// and never straddle the 16-wide tile boundary.
__global__ void __launch_bounds__(256)
gather_kernel(const float4* __restrict__ tiles, float4* __restrict__ out, int nquads)
{
    int tid = blockIdx.x * 256 + threadIdx.x;        // quad index (fits int: 12.8M)
    if (tid >= nquads) return;

    int zq = tid & 15;                 // z = zq*4
    int t1 = tid >> 4;
    int y  = t1 & 63;
    int t2 = t1 >> 6;
    int x  = t2 & 63;
    int jc = t2 >> 6;                  // 0..195  (j*CH + c)

    int gx = x + S0, gy = y + S0, gz = zq * 4 + S0;
    int tx = gx >> 4, ty = gy >> 4, tz = gz >> 4;
    int lx = gx & 15, ly = gy & 15, lz = gz & 15;   // lz multiple of 4

    int tm = g_tile_map[(tx * NT + ty) * NT + tz];

    float4 v = make_float4(0.f, 0.f, 0.f, 0.f);
    if (tm >= 0) {
        // element offset: ((tm*7+j)*28+c)*4096 + (lx*16+ly)*16 + lz ; /4 -> quads
        // (tm*SUBB*CH + jc) covers j,c jointly since jc = j*CH + c.
        long elem = ((long)tm * (SUBB * CH) + jc) * TILE_EL
                  + (lx * 16 + ly) * 16 + lz;
        v = tiles[elem >> 2];
    }
    out[tid] = v;
}

extern "C" void kernel_launch(void* const* d_in, const int* in_sizes, int n_in,
                              void* d_out, int out_size)
{
    const float*         tiles = (const float*)d_in[0];
    const unsigned char* occ   = (const unsigned char*)d_in[1];

    int n_occ = in_sizes[0] / (SUBB * CH * TILE_EL);

    setup_kernel<<<1, 32>>>(occ, n_occ);

    int nquads = out_size / 4;                      // 12,845,056
    int nblocks = (nquads + 255) / 256;             // 50,176
    gather_kernel<<<nblocks, 256>>>((const float4*)tiles, (float4*)d_out, nquads);
}

// round 2
// speedup vs baseline: 1.2820x; 1.2820x over previous
#include <cuda_runtime.h>

// Problem constants (fixed by reference_code)
#define T_GRID   8          // occupancy grid is 8x8x8 = 512
#define SUBB     7
#define CH       28
#define TILE_EL  4096       // 16*16*16
#define NT       5          // region spans tiles [0,5) per dim (slice 8..72)
#define S0       8          // slice start offset
#define QPT      4          // quads per thread in gather
// output: (7,1,28,64,64,64) = 51,380,224 floats = 12,845,056 float4 quads

__device__ int g_tile_map[NT * NT * NT];   // tile index or -1

// Parallel setup: 1 block x 512 threads.
// Detect occupancy dtype (u8 vs i32) by popcount of the byte view, then
// ballot/popcount prefix scan -> tile index per occupied slot -> region map.
__global__ void setup_kernel(const unsigned char* __restrict__ occ_bytes, int n_occ)
{
    __shared__ int s_wcnt[16];
    __shared__ int s_wexcl[16];
    __shared__ int s_flag;
    __shared__ int s_pref[T_GRID * T_GRID * T_GRID];

    const int t    = threadIdx.x;         // 0..511
    const int lane = t & 31;
    const int w    = t >> 5;              // 0..15

    // ---- dtype detection: popcount of all 512 bytes ----
    int b8 = (occ_bytes[t] != 0);
    unsigned bal = __ballot_sync(0xffffffffu, b8);
    if (lane == 0) s_wcnt[w] = __popc(bal);
    __syncthreads();
    if (t == 0) {
        int c = 0;
        #pragma unroll
        for (int i = 0; i < 16; i++) c += s_wcnt[i];
        s_flag = (c == n_occ);            // true -> byte layout
    }
    __syncthreads();

    // ---- occupancy bit under the detected layout ----
    int o = s_flag ? b8 : (((const int*)occ_bytes)[t] != 0);

    // ---- inclusive prefix sum over 512 flags ----
    unsigned bal2 = __ballot_sync(0xffffffffu, o);
    int wp = __popc(bal2 & ((2u << lane) - 1u));   // inclusive within warp
    if (lane == 31) s_wcnt[w] = __popc(bal2);
    __syncthreads();
    if (t == 0) {
        int run = 0;
        #pragma unroll
        for (int i = 0; i < 16; i++) { s_wexcl[i] = run; run += s_wcnt[i]; }
    }
    __syncthreads();

    int incl = s_wexcl[w] + wp;                    // inclusive count up to t
    s_pref[t] = o ? (incl - 1) : -1;               // tile index or -1
    __syncthreads();

    // ---- region tile map: 125 entries ----
    if (t < NT * NT * NT) {
        int tz = t % NT;
        int r  = t / NT;
        int ty = r % NT;
        int tx = r / NT;
        int lin = (tx * T_GRID + ty) * T_GRID + tz;   // t_start = 0 offset? no:
        // region tiles are grid tiles [0..4] since t_start = S0/BLOCK = 0? S0=8 -> t_start=0
        g_tile_map[t] = s_pref[lin];
    }
}

// Gather: each thread copies QPT=4 independent float4 quads (grid-stride),
// batched LDG.128s for MLP, fully coalesced STG.128s.
// quad id bit layout: [0:4)=z-quad, [4:10)=y, [10:16)=x, [16:..)=jc (j*28+c)
__global__ void __launch_bounds__(256)
gather_kernel(const float4* __restrict__ tiles, float4* __restrict__ out, int nquads)
{
    const int total = gridDim.x * 256;
    const int base  = blockIdx.x * 256 + threadIdx.x;

    #pragma unroll
    for (int k = 0; k < QPT; k++) {
        int q = base + k * total;
        if (q >= nquads) break;

        int zq = q & 15;                 // z = zq*4
        int t1 = q >> 4;
        int y  = t1 & 63;
        int t2 = t1 >> 6;
        int x  = t2 & 63;
        int jc = t2 >> 6;                // 0..195  (j*CH + c)

        int gx = x + S0, gy = y + S0, gz = zq * 4 + S0;
        int tx = gx >> 4, ty = gy >> 4, tz = gz >> 4;
        int lx = gx & 15, ly = gy & 15, lz = gz & 15;   // lz multiple of 4

        int tm = g_tile_map[(tx * NT + ty) * NT + tz];

        float4 v = make_float4(0.f, 0.f, 0.f, 0.f);
        if (tm >= 0) {
            long elem = ((long)tm * (SUBB * CH) + jc) * TILE_EL
                      + (lx * 16 + ly) * 16 + lz;
            v = tiles[elem >> 2];
        }
        out[q] = v;
    }
}

extern "C" void kernel_launch(void* const* d_in, const int* in_sizes, int n_in,
                              void* d_out, int out_size)
{
    const float*         tiles = (const float*)d_in[0];
    const unsigned char* occ   = (const unsigned char*)d_in[1];

    int n_occ = in_sizes[0] / (SUBB * CH * TILE_EL);

    setup_kernel<<<1, 512>>>(occ, n_occ);

    int nquads  = out_size / 4;                          // 12,845,056
    int nthreads = (nquads + QPT - 1) / QPT;             // 3,211,264
    int nblocks  = (nthreads + 255) / 256;               // 12,544
    gather_kernel<<<nblocks, 256>>>((const float4*)tiles, (float4*)d_out, nquads);
}

// round 3
// speedup vs baseline: 1.4238x; 1.1106x over previous
#include <cuda_runtime.h>

// Problem constants (fixed by reference_code)
#define T_GRID   8          // occupancy grid 8x8x8 = 512
#define SUBB     7
#define CH       28
#define JC       (SUBB*CH)  // 196
#define NT       5          // region tiles [0,5) per dim (slice 8..72, t_start=0)
#define S0       8
#define QPT      8          // quads per thread
// output: (7,1,28,64,64,64) = 51,380,224 floats = 12,845,056 float4 quads
// tiles quads total: 154*196*1024 = 30,908,416 < 2^31  -> int addressing OK

// Build the 125-entry tile map (tile index or -1) in SMEM from occupancy.
// Warp 0 builds a 512-bit mask; dtype (u8 vs i32) auto-detected via popcount.
__device__ __forceinline__ void build_map(const unsigned char* __restrict__ occ,
                                          int n_occ, unsigned* s_mask, int* s_map)
{
    const int t = threadIdx.x;
    if (t < 32) {
        const int lane = t;
        // byte-layout view: 512 bytes, 16 per lane
        uint4 v = ((const uint4*)occ)[lane];
        unsigned w[4] = {v.x, v.y, v.z, v.w};
        unsigned m16 = 0;
        #pragma unroll
        for (int i = 0; i < 4; i++)
            #pragma unroll
            for (int j = 0; j < 4; j++)
                m16 |= (unsigned)(((w[i] >> (8*j)) & 0xffu) != 0) << (i*4 + j);
        // total popcount across warp -> dtype check
        int cnt = __popc(m16);
        #pragma unroll
        for (int o = 16; o > 0; o >>= 1) cnt += __shfl_xor_sync(0xffffffffu, cnt, o);
        if (cnt != n_occ) {
            // int32 layout: 512 ints, 16 per lane
            const int4* q = (const int4*)occ;
            m16 = 0;
            #pragma unroll
            for (int i = 0; i < 4; i++) {
                int4 ww = q[lane*4 + i];
                m16 |= (unsigned)(ww.x != 0) << (4*i)
                     | (unsigned)(ww.y != 0) << (4*i + 1)
                     | (unsigned)(ww.z != 0) << (4*i + 2)
                     | (unsigned)(ww.w != 0) << (4*i + 3);
            }
        }
        // combine lane pairs (2j,2j+1) -> 32-bit word j
        unsigned other = __shfl_xor_sync(0xffffffffu, m16, 1);
        if ((lane & 1) == 0) s_mask[lane >> 1] = (m16 & 0xffffu) | (other << 16);
    }
    __syncthreads();
    if (t < NT*NT*NT) {
        int tz = t % NT, r = t / NT;
        int ty = r % NT, tx = r / NT;
        int lin = (tx * T_GRID + ty) * T_GRID + tz;
        int wq = lin >> 5, bit = lin & 31;
        int pre = 0;
        for (int w = 0; w < wq; w++) pre += __popc(s_mask[w]);
        pre += __popc(s_mask[wq] & ((1u << bit) - 1u));
        int occd = (s_mask[wq] >> bit) & 1;
        s_map[t] = occd ? pre : -1;
    }
    __syncthreads();
}

// Fused gather: per-block map build, then guard-free QPT=8 batched copy.
// quad id bits: [0:4)=z-quad, [4:10)=y, [10:16)=x, [16:..)=jc
__global__ void __launch_bounds__(256)
gather_fused(const float4* __restrict__ tiles, float4* __restrict__ out,
             const unsigned char* __restrict__ occ, int n_occ)
{
    __shared__ unsigned s_mask[16];
    __shared__ int s_map[NT*NT*NT];
    build_map(occ, n_occ, s_mask, s_map);

    const int total = gridDim.x * 256;
    const int base  = blockIdx.x * 256 + threadIdx.x;

    int src[QPT];   // source quad index, or <0 if zero-fill
    #pragma unroll
    for (int k = 0; k < QPT; k++) {
        int q  = base + k * total;
        int zq = q & 15;
        int t1 = q >> 4;
        int y  = t1 & 63;
        int t2 = t1 >> 6;
        int x  = t2 & 63;
        int jc = t2 >> 6;

        int gx = x + S0, gy = y + S0, gz = zq * 4 + S0;
        int tx = gx >> 4, ty = gy >> 4, tz = gz >> 4;
        int lx = gx & 15, ly = gy & 15, lz = gz & 15;

        int tm = s_map[(tx * NT + ty) * NT + tz];
        // quad offset inside tile: ((lx*16+ly)*16+lz)/4
        int qoff = (lx * 16 + ly) * 4 + (lz >> 2);
        src[k] = (tm >= 0) ? (((tm * JC + jc) << 10) | qoff) : -1;
    }

    float4 v[QPT];
    #pragma unroll
    for (int k = 0; k < QPT; k++) {
        v[k] = make_float4(0.f, 0.f, 0.f, 0.f);
        if (src[k] >= 0) v[k] = tiles[src[k]];
    }

    #pragma unroll
    for (int k = 0; k < QPT; k++)
        out[base + k * total] = v[k];
}

// Guarded 1-quad/thread tail (only launched if nquads isn't divisible; it is).
__global__ void __launch_bounds__(256)
gather_tail(const float4* __restrict__ tiles, float4* __restrict__ out,
            const unsigned char* __restrict__ occ, int n_occ,
            int start, int nquads)
{
    __shared__ unsigned s_mask[16];
    __shared__ int s_map[NT*NT*NT];
    build_map(occ, n_occ, s_mask, s_map);

    int q = start + blockIdx.x * 256 + threadIdx.x;
    if (q >= nquads) return;
    int zq = q & 15;
    int t1 = q >> 4;
    int y  = t1 & 63;
    int t2 = t1 >> 6;
    int x  = t2 & 63;
    int jc = t2 >> 6;
    int gx = x + S0, gy = y + S0, gz = zq * 4 + S0;
    int tm = s_map[((gx >> 4) * NT + (gy >> 4)) * NT + (gz >> 4)];
    float4 v = make_float4(0.f, 0.f, 0.f, 0.f);
    if (tm >= 0)
        v = tiles[((tm * JC + jc) << 10) | (((gx & 15) * 16 + (gy & 15)) * 4 + ((gz & 15) >> 2))];
    out[q] = v;
}

extern "C" void kernel_launch(void* const* d_in, const int* in_sizes, int n_in,
                              void* d_out, int out_size)
{
    const float*         tiles = (const float*)d_in[0];
    const unsigned char* occ   = (const unsigned char*)d_in[1];

    int n_occ  = in_sizes[0] / (JC * 4096);
    int nquads = out_size / 4;                       // 12,845,056

    int per_block = 256 * QPT;                       // 2048
    int nblocks   = nquads / per_block;              // 6272 (exact)
    int covered   = nblocks * per_block;

    if (nblocks > 0)
        gather_fused<<<nblocks, 256>>>((const float4*)tiles, (float4*)d_out, occ, n_occ);

    if (covered < nquads) {
        int rem = nquads - covered;
        gather_tail<<<(rem + 255) / 256, 256>>>((const float4*)tiles, (float4*)d_out,
                                                occ, n_occ, covered, nquads);
    }
}